// round 10
// baseline (speedup 1.0000x reference)
#include <cuda_runtime.h>
#include <cuda_bf16.h>

// Problem constants (from reference setup_inputs)
#define B  4
#define C  64
#define H  128
#define W  128
#define O  64
#define KH 3
#define KW 3
#define K  9          // KH*KW
#define CK (C*K)      // 576
#define HW (H*W)      // 16384
#define NPIX (B*HW)   // 65536

#define TILE_P 32
#define NTHREADS 256
#define CB_T 16       // wq chunk: 16 blocks of 4 kc = 64 kc, 9 chunks

// Packed dual-FMA (sm_103a): d = a*b + d on two f32 lanes in one issue.
#define FMA2(d, a, b) asm("fma.rn.f32x2 %0, %1, %2, %0;" : "+l"(d) : "l"(a), "l"(b))

// Scratch (allocation-free rule: __device__ globals)
__device__ float g_xt[B * HW * C];        // NHWC input, 16.8MB
__device__ float g_wq[CK * O];            // weight [kc/4][O][4], kc = k*64+c, 147KB
__device__ float g_val[NPIX * CK];        // sampled columns [P][K][C], 151MB

// ---------------------------------------------------------------------------
// Kernel A: NCHW -> NHWC transpose
// ---------------------------------------------------------------------------
__global__ void transpose_kernel(const float* __restrict__ x) {
    __shared__ float tile[32][33];
    int b  = blockIdx.z;
    int c0 = blockIdx.y * 32;
    int s0 = blockIdx.x * 32;
    int tx = threadIdx.x, ty = threadIdx.y;   // block (32, 8)
    #pragma unroll
    for (int i = 0; i < 32; i += 8)
        tile[ty + i][tx] = x[(b * C + c0 + ty + i) * HW + s0 + tx];
    __syncthreads();
    #pragma unroll
    for (int i = 0; i < 32; i += 8)
        g_xt[(b * HW + s0 + ty + i) * C + c0 + tx] = tile[tx][ty + i];
}

// ---------------------------------------------------------------------------
// Kernel B: weight repack  W[o][c][kh][kw] -> Wq[kcb][o][i], kc=kcb*4+i=k*64+c
// ---------------------------------------------------------------------------
__global__ void wq_kernel(const float* __restrict__ w) {
    int idx = blockIdx.x * 256 + threadIdx.x;
    if (idx < CK * O) {
        int i   = idx & 3;
        int o   = (idx >> 2) & (O - 1);
        int kcb = idx >> 8;
        int kc  = kcb * 4 + i;
        int c   = kc & (C - 1);
        int k   = kc >> 6;
        g_wq[idx] = w[(o * C + c) * K + k];
    }
}

// ---------------------------------------------------------------------------
// Kernel C: sampling. Free-running, no barriers. One CTA = (b, ho, 32 wo).
// Warp-task = (k, pixel); lane = channel pair. Writes 256B coalesced rows.
// ---------------------------------------------------------------------------
__global__ __launch_bounds__(NTHREADS)
void sample_kernel(const float* __restrict__ offset,
                   const float* __restrict__ mask) {
    const int wo0 = blockIdx.x * TILE_P;
    const int ho  = blockIdx.y;
    const int b   = blockIdx.z;
    const int warpId = threadIdx.x >> 5;
    const int lane   = threadIdx.x & 31;

    const float* xb = g_xt + b * HW * C;
    const int coff = lane * 2;

    #pragma unroll 2
    for (int i = 0; i < (K * TILE_P) / 8; i++) {   // 36 tasks per warp
        int t = warpId * 36 + i;
        int k = t >> 5;
        int p = t & 31;
        int wo = wo0 + p;

        // warp-uniform scalar params (broadcast loads)
        float offy = __ldg(&offset[((b * 2 * K + 2 * k    ) * H + ho) * W + wo]);
        float offx = __ldg(&offset[((b * 2 * K + 2 * k + 1) * H + ho) * W + wo]);
        float m    = __ldg(&mask  [((b * K + k) * H + ho) * W + wo]);
        float py = offy + (float)(k / KW) + (float)(ho - 1);   // sh=dh=1, ph=1
        float px = offx + (float)(k % KW) + (float)(wo - 1);
        float y0f = floorf(py), x0f = floorf(px);
        float ly = py - y0f, lx = px - x0f;
        int y0 = (int)y0f, x0 = (int)x0f;
        float w00 = (1.f - ly) * (1.f - lx) * m;
        float w01 = (1.f - ly) * lx * m;
        float w10 = ly * (1.f - lx) * m;
        float w11 = ly * lx * m;

        bool yv0 = (unsigned)y0 < H;
        bool yv1 = (unsigned)(y0 + 1) < H;
        bool xv0 = (unsigned)x0 < W;
        bool xv1 = (unsigned)(x0 + 1) < W;

        float2 v00 = {0.f, 0.f}, v01 = {0.f, 0.f}, v10 = {0.f, 0.f}, v11 = {0.f, 0.f};
        if (yv0 && xv0) v00 = *(const float2*)(xb + ((y0    ) * W + x0    ) * C + coff);
        if (yv0 && xv1) v01 = *(const float2*)(xb + ((y0    ) * W + x0 + 1) * C + coff);
        if (yv1 && xv0) v10 = *(const float2*)(xb + ((y0 + 1) * W + x0    ) * C + coff);
        if (yv1 && xv1) v11 = *(const float2*)(xb + ((y0 + 1) * W + x0 + 1) * C + coff);

        float2 r;
        r.x = w00 * v00.x + w01 * v01.x + w10 * v10.x + w11 * v11.x;
        r.y = w00 * v00.y + w01 * v01.y + w10 * v10.y + w11 * v11.y;

        int P = b * HW + ho * W + wo;
        *(float2*)(g_val + P * CK + k * C + coff) = r;   // warp: 256B contiguous
    }
}

// ---------------------------------------------------------------------------
// Kernel D: GEMM  out[o][P] = sum_kc wq[kc][o] * val[P][kc]  (+bias)
// CTA = 32 pixels; 8 warps = 2 o-halves x 4 pixel-groups; 8 px/thread, FMA2.
// ---------------------------------------------------------------------------
__global__ __launch_bounds__(NTHREADS)
void gemm_kernel(const float* __restrict__ bias, float* __restrict__ out) {
    __shared__ float wq_s[CB_T * O * 4];   // 16KB chunk

    const int wo0 = blockIdx.x * TILE_P;
    const int ho  = blockIdx.y;
    const int b   = blockIdx.z;
    const int tid    = threadIdx.x;
    const int warpId = tid >> 5;
    const int lane   = tid & 31;

    const int h = warpId & 1;          // o half
    const int g = warpId >> 1;         // pixel group (8 px)
    const int o = h * 32 + lane;

    unsigned long long acc[8];
    #pragma unroll
    for (int p = 0; p < 8; p++) acc[p] = 0ull;

    const int P0 = b * HW + ho * W + wo0 + g * 8;
    const float* vbase = g_val + P0 * CK;
    const float4* gwq4 = (const float4*)g_wq;
    float4* wq_s4 = (float4*)wq_s;

    #pragma unroll 1
    for (int ch = 0; ch < (CK / 4) / CB_T; ch++) {   // 9 chunks
        if (ch) __syncthreads();
        #pragma unroll
        for (int t = 0; t < (CB_T * O) / NTHREADS; t++)
            wq_s4[t * NTHREADS + tid] = gwq4[ch * CB_T * O + t * NTHREADS + tid];
        __syncthreads();

        #pragma unroll 2
        for (int i = 0; i < CB_T; i++) {
            ulonglong2 wv = *(const ulonglong2*)(wq_s + (i * O + o) * 4);
            const float* vp = vbase + (ch * CB_T + i) * 4;
            #pragma unroll
            for (int p = 0; p < 8; p++) {
                ulonglong2 v = *(const ulonglong2*)(vp + p * CK);
                FMA2(acc[p], wv.x, v.x);
                FMA2(acc[p], wv.y, v.y);
            }
        }
    }

    float bv = bias[o];
    float r[8];
    #pragma unroll
    for (int p = 0; p < 8; p++) {
        float2 a = *(float2*)&acc[p];
        r[p] = a.x + a.y + bv;
    }
    float* ob = out + ((size_t)(b * O + o)) * HW + ho * W + wo0 + g * 8;
    *(float4*)(ob)     = make_float4(r[0], r[1], r[2], r[3]);
    *(float4*)(ob + 4) = make_float4(r[4], r[5], r[6], r[7]);
}

// ---------------------------------------------------------------------------
extern "C" void kernel_launch(void* const* d_in, const int* in_sizes, int n_in,
                              void* d_out, int out_size) {
    const float* x      = (const float*)d_in[0];
    const float* offset = (const float*)d_in[1];
    const float* mask   = (const float*)d_in[2];
    const float* weight = (const float*)d_in[3];
    const float* bias   = (const float*)d_in[4];
    float* out = (float*)d_out;

    {   // A: transpose to NHWC
        dim3 grid(HW / 32, C / 32, B);
        dim3 block(32, 8);
        transpose_kernel<<<grid, block>>>(x);
    }
    {   // B: weight repack
        wq_kernel<<<(CK * O + 255) / 256, 256>>>(weight);
    }
    {   // C: sampling
        dim3 grid(W / TILE_P, H, B);
        sample_kernel<<<grid, NTHREADS>>>(offset, mask);
    }
    {   // D: GEMM
        dim3 grid(W / TILE_P, H, B);
        gemm_kernel<<<grid, NTHREADS>>>(bias, out);
    }
}

// round 11
// speedup vs baseline: 1.3728x; 1.3728x over previous
#include <cuda_runtime.h>
#include <cuda_bf16.h>

// Problem constants
#define B  4
#define C  64
#define H  128
#define W  128
#define O  64
#define KH 3
#define KW 3
#define K  9
#define CK (C*K)      // 576
#define HW (H*W)      // 16384
#define NPIX (B*HW)   // 65536

#define TILE_P 32     // sampler tile
#define NTHREADS 256

// GEMM tiling
#define GP  128       // pixels per CTA (one output row)
#define GKC 64        // kc chunk
#define NCHUNK (CK/GKC)   // 9

// Packed dual-FMA (sm_103a): d = a*b + d on two f32 lanes in one issue.
#define FMA2(d, a, b) asm("fma.rn.f32x2 %0, %1, %2, %0;" : "+l"(d) : "l"(a), "l"(b))
#define PACK2(d, s)   asm("mov.b64 %0, {%1, %1};" : "=l"(d) : "r"(s))

// Scratch (__device__ globals per allocation rules)
__device__ float g_xt[B * HW * C];        // NHWC input, 16.8MB
__device__ float g_wt[CK * O];            // weight [kc][o], kc = k*64+c, 147KB
__device__ float g_val[NPIX * CK];        // sampled columns [P][kc], 151MB

// ---------------------------------------------------------------------------
// Kernel A: NCHW -> NHWC transpose
// ---------------------------------------------------------------------------
__global__ void transpose_kernel(const float* __restrict__ x) {
    __shared__ float tile[32][33];
    int b  = blockIdx.z;
    int c0 = blockIdx.y * 32;
    int s0 = blockIdx.x * 32;
    int tx = threadIdx.x, ty = threadIdx.y;   // block (32, 8)
    #pragma unroll
    for (int i = 0; i < 32; i += 8)
        tile[ty + i][tx] = x[(b * C + c0 + ty + i) * HW + s0 + tx];
    __syncthreads();
    #pragma unroll
    for (int i = 0; i < 32; i += 8)
        g_xt[(b * HW + s0 + ty + i) * C + c0 + tx] = tile[tx][ty + i];
}

// ---------------------------------------------------------------------------
// Kernel B: weight repack  W[o][c][kh][kw] -> Wt[kc][o], kc = k*64 + c
// ---------------------------------------------------------------------------
__global__ void wt_kernel(const float* __restrict__ w) {
    int idx = blockIdx.x * 256 + threadIdx.x;
    if (idx < CK * O) {
        int o  = idx & (O - 1);
        int kc = idx >> 6;
        int c  = kc & (C - 1);
        int k  = kc >> 6;
        g_wt[idx] = w[(o * C + c) * K + k];
    }
}

// ---------------------------------------------------------------------------
// Kernel C: sampling. Free-running. CTA = (b, ho, 32 wo); warp-task = (k, px);
// lane = channel pair. Writes 256B coalesced rows val[P][k*64+c].
// ---------------------------------------------------------------------------
__global__ __launch_bounds__(NTHREADS)
void sample_kernel(const float* __restrict__ offset,
                   const float* __restrict__ mask) {
    const int wo0 = blockIdx.x * TILE_P;
    const int ho  = blockIdx.y;
    const int b   = blockIdx.z;
    const int warpId = threadIdx.x >> 5;
    const int lane   = threadIdx.x & 31;

    const float* xb = g_xt + b * HW * C;
    const int coff = lane * 2;

    #pragma unroll 2
    for (int i = 0; i < (K * TILE_P) / 8; i++) {   // 36 tasks per warp
        int t = warpId * 36 + i;
        int k = t >> 5;
        int p = t & 31;
        int wo = wo0 + p;

        float offy = __ldg(&offset[((b * 2 * K + 2 * k    ) * H + ho) * W + wo]);
        float offx = __ldg(&offset[((b * 2 * K + 2 * k + 1) * H + ho) * W + wo]);
        float m    = __ldg(&mask  [((b * K + k) * H + ho) * W + wo]);
        float py = offy + (float)(k / KW) + (float)(ho - 1);   // sh=dh=1, ph=1
        float px = offx + (float)(k % KW) + (float)(wo - 1);
        float y0f = floorf(py), x0f = floorf(px);
        float ly = py - y0f, lx = px - x0f;
        int y0 = (int)y0f, x0 = (int)x0f;
        float w00 = (1.f - ly) * (1.f - lx) * m;
        float w01 = (1.f - ly) * lx * m;
        float w10 = ly * (1.f - lx) * m;
        float w11 = ly * lx * m;

        bool yv0 = (unsigned)y0 < H;
        bool yv1 = (unsigned)(y0 + 1) < H;
        bool xv0 = (unsigned)x0 < W;
        bool xv1 = (unsigned)(x0 + 1) < W;

        float2 v00 = {0.f, 0.f}, v01 = {0.f, 0.f}, v10 = {0.f, 0.f}, v11 = {0.f, 0.f};
        if (yv0 && xv0) v00 = *(const float2*)(xb + ((y0    ) * W + x0    ) * C + coff);
        if (yv0 && xv1) v01 = *(const float2*)(xb + ((y0    ) * W + x0 + 1) * C + coff);
        if (yv1 && xv0) v10 = *(const float2*)(xb + ((y0 + 1) * W + x0    ) * C + coff);
        if (yv1 && xv1) v11 = *(const float2*)(xb + ((y0 + 1) * W + x0 + 1) * C + coff);

        float2 r;
        r.x = w00 * v00.x + w01 * v01.x + w10 * v10.x + w11 * v11.x;
        r.y = w00 * v00.y + w01 * v01.y + w10 * v10.y + w11 * v11.y;

        int P = b * HW + ho * W + wo;
        *(float2*)(g_val + (size_t)P * CK + k * C + coff) = r;
    }
}

// ---------------------------------------------------------------------------
// Kernel D: register-tiled GEMM. CTA = 64 o x 128 px; thread = 8 o x 4 px.
// sv[kc][px] (transposed in smem), sw[kc][o]. Inner: per-lane-distinct LDS.128.
// ---------------------------------------------------------------------------
__global__ __launch_bounds__(NTHREADS)
void gemm_kernel(const float* __restrict__ bias, float* __restrict__ out) {
    extern __shared__ float smem[];
    float* sv = smem;                 // [GKC][GP] = 64*128 floats (32KB)
    float* sw = smem + GKC * GP;      // [GKC][O]  = 64*64  floats (16KB)

    const int tid  = threadIdx.x;
    const int pix0 = blockIdx.x * GP;       // linear pixel base (same b, same row)
    const int to   = tid & 7;               // o-octet: o = to*8 .. to*8+7
    const int tp   = tid >> 3;              // px-quad: px = tp*4 .. tp*4+3

    unsigned long long acc[4][4];           // [o-pair][px], f32x2 over adjacent o
    #pragma unroll
    for (int i = 0; i < 4; i++)
        #pragma unroll
        for (int j = 0; j < 4; j++) acc[i][j] = 0ull;

    // val staging mapping: 2 threads per pixel row, 8 float4s each
    const int vP    = tid >> 1;             // 0..127
    const int vhalf = tid & 1;              // half of the 64-kc chunk
    const float* vrow = g_val + (size_t)(pix0 + vP) * CK + vhalf * 32;

    #pragma unroll 1
    for (int ch = 0; ch < NCHUNK; ch++) {
        if (ch) __syncthreads();
        // stage weights: 16KB linear, coalesced
        {
            const float4* gw4 = (const float4*)(g_wt + ch * GKC * O);
            float4* sw4 = (float4*)sw;
            #pragma unroll
            for (int j = 0; j < (GKC * O / 4) / NTHREADS; j++)   // 4 passes
                sw4[j * NTHREADS + tid] = gw4[j * NTHREADS + tid];
        }
        // stage val chunk transposed: sv[kc][px]
        {
            const float4* vr4 = (const float4*)(vrow + ch * GKC);
            #pragma unroll
            for (int q = 0; q < 8; q++) {
                float4 v = vr4[q];
                int kcl = vhalf * 32 + q * 4;
                sv[(kcl    ) * GP + vP] = v.x;
                sv[(kcl + 1) * GP + vP] = v.y;
                sv[(kcl + 2) * GP + vP] = v.z;
                sv[(kcl + 3) * GP + vP] = v.w;
            }
        }
        __syncthreads();

        #pragma unroll 4
        for (int kc = 0; kc < GKC; kc++) {
            // weights: 8 consecutive o = 4 natural f32x2 pairs
            ulonglong2 wa = *(const ulonglong2*)(sw + kc * O + to * 8);
            ulonglong2 wb = *(const ulonglong2*)(sw + kc * O + to * 8 + 4);
            float4 v = *(const float4*)(sv + kc * GP + tp * 4);
            unsigned long long vv0, vv1, vv2, vv3;
            PACK2(vv0, __float_as_uint(v.x));
            PACK2(vv1, __float_as_uint(v.y));
            PACK2(vv2, __float_as_uint(v.z));
            PACK2(vv3, __float_as_uint(v.w));
            FMA2(acc[0][0], wa.x, vv0); FMA2(acc[0][1], wa.x, vv1);
            FMA2(acc[0][2], wa.x, vv2); FMA2(acc[0][3], wa.x, vv3);
            FMA2(acc[1][0], wa.y, vv0); FMA2(acc[1][1], wa.y, vv1);
            FMA2(acc[1][2], wa.y, vv2); FMA2(acc[1][3], wa.y, vv3);
            FMA2(acc[2][0], wb.x, vv0); FMA2(acc[2][1], wb.x, vv1);
            FMA2(acc[2][2], wb.x, vv2); FMA2(acc[2][3], wb.x, vv3);
            FMA2(acc[3][0], wb.y, vv0); FMA2(acc[3][1], wb.y, vv1);
            FMA2(acc[3][2], wb.y, vv2); FMA2(acc[3][3], wb.y, vv3);
        }
    }

    // Epilogue: acc[op][p] = (out[o0], out[o0+1]) at px = tp*4+p
    const int b   = pix0 >> 14;             // / HW
    const int hw0 = pix0 & (HW - 1);
    float* ob = out + ((size_t)(b * O) << 14) + hw0 + tp * 4;
    #pragma unroll
    for (int op = 0; op < 4; op++) {
        int o0 = to * 8 + op * 2;
        float b0 = bias[o0], b1 = bias[o0 + 1];
        float2 a0 = *(float2*)&acc[op][0];
        float2 a1 = *(float2*)&acc[op][1];
        float2 a2 = *(float2*)&acc[op][2];
        float2 a3 = *(float2*)&acc[op][3];
        *(float4*)(ob + (size_t)o0 * HW)       = make_float4(a0.x + b0, a1.x + b0, a2.x + b0, a3.x + b0);
        *(float4*)(ob + (size_t)(o0 + 1) * HW) = make_float4(a0.y + b1, a1.y + b1, a2.y + b1, a3.y + b1);
    }
}

// ---------------------------------------------------------------------------
extern "C" void kernel_launch(void* const* d_in, const int* in_sizes, int n_in,
                              void* d_out, int out_size) {
    const float* x      = (const float*)d_in[0];
    const float* offset = (const float*)d_in[1];
    const float* mask   = (const float*)d_in[2];
    const float* weight = (const float*)d_in[3];
    const float* bias   = (const float*)d_in[4];
    float* out = (float*)d_out;

    {   // A: transpose to NHWC
        dim3 grid(HW / 32, C / 32, B);
        dim3 block(32, 8);
        transpose_kernel<<<grid, block>>>(x);
    }
    {   // B: weight repack [kc][o]
        wt_kernel<<<(CK * O + 255) / 256, 256>>>(weight);
    }
    {   // C: sampling
        dim3 grid(W / TILE_P, H, B);
        sample_kernel<<<grid, NTHREADS>>>(offset, mask);
    }
    {   // D: GEMM
        int smem_bytes = (GKC * GP + GKC * O) * sizeof(float);   // 48KB + 16KB... = 49152+16384? no: 32768+16384 = 49152
        cudaFuncSetAttribute(gemm_kernel,
                             cudaFuncAttributeMaxDynamicSharedMemorySize, smem_bytes);
        gemm_kernel<<<NPIX / GP, NTHREADS, smem_bytes>>>(bias, out);
    }
}

// round 13
// speedup vs baseline: 2.7150x; 1.9777x over previous
#include <cuda_runtime.h>
#include <cuda_bf16.h>
#include <cstdint>

// Problem constants
#define B  4
#define C  64
#define H  128
#define W  128
#define O  64
#define KH 3
#define KW 3
#define K  9
#define CK (C*K)      // 576
#define HW (H*W)      // 16384
#define NPIX (B*HW)   // 65536

#define TILE_P 32         // sampler tile
#define GPX 128           // GEMM pixels per tile (one image row)
#define NTILES (NPIX/GPX) // 512
#define NCH 9             // kc chunks of 64 (== tap k)

// Padded smem row stride: 64 bf16 + 8 pad = 72 bf16 = 144 bytes
#define SSTR 144

// Scratch (__device__ globals per allocation rules)
__device__ float          g_xt[B * HW * C];        // NHWC input fp32, 16.8MB
__device__ __nv_bfloat16  g_vh[(size_t)NPIX * CK]; // val hi, [tile][k][px][c], 75.5MB
__device__ __nv_bfloat16  g_vl[(size_t)NPIX * CK]; // val lo
__device__ __nv_bfloat16  g_wh[K * O * C];         // weight hi, [k][o][c]
__device__ __nv_bfloat16  g_wl[K * O * C];         // weight lo

// ---------------- PTX helpers ----------------
__device__ __forceinline__ uint32_t smem_u32(const void* p) {
    uint32_t a;
    asm("{ .reg .u64 t; cvta.to.shared.u64 t, %1; cvt.u32.u64 %0, t; }" : "=r"(a) : "l"(p));
    return a;
}
__device__ __forceinline__ void ldsm_x4(uint32_t* r, uint32_t addr) {
    asm volatile("ldmatrix.sync.aligned.m8n8.x4.shared.b16 {%0,%1,%2,%3}, [%4];"
        : "=r"(r[0]), "=r"(r[1]), "=r"(r[2]), "=r"(r[3]) : "r"(addr));
}
__device__ __forceinline__ void ldsm_x2(uint32_t* r, uint32_t addr) {
    asm volatile("ldmatrix.sync.aligned.m8n8.x2.shared.b16 {%0,%1}, [%2];"
        : "=r"(r[0]), "=r"(r[1]) : "r"(addr));
}
__device__ __forceinline__ void mma16816(float* d, const uint32_t* a, const uint32_t* b) {
    asm volatile("mma.sync.aligned.m16n8k16.row.col.f32.bf16.bf16.f32 "
        "{%0,%1,%2,%3}, {%4,%5,%6,%7}, {%8,%9}, {%0,%1,%2,%3};"
        : "+f"(d[0]), "+f"(d[1]), "+f"(d[2]), "+f"(d[3])
        : "r"(a[0]), "r"(a[1]), "r"(a[2]), "r"(a[3]), "r"(b[0]), "r"(b[1]));
}

// ---------------------------------------------------------------------------
// Kernel A: NCHW -> NHWC transpose (fp32, sampler input)
// ---------------------------------------------------------------------------
__global__ void transpose_kernel(const float* __restrict__ x) {
    __shared__ float tile[32][33];
    int b  = blockIdx.z;
    int c0 = blockIdx.y * 32;
    int s0 = blockIdx.x * 32;
    int tx = threadIdx.x, ty = threadIdx.y;   // block (32, 8)
    #pragma unroll
    for (int i = 0; i < 32; i += 8)
        tile[ty + i][tx] = x[(b * C + c0 + ty + i) * HW + s0 + tx];
    __syncthreads();
    #pragma unroll
    for (int i = 0; i < 32; i += 8)
        g_xt[(b * HW + s0 + ty + i) * C + c0 + tx] = tile[tx][ty + i];
}

// ---------------------------------------------------------------------------
// Kernel B: weight split+repack  W[o][c][k] -> Wh/Wl [k][o][c] bf16
// ---------------------------------------------------------------------------
__global__ void wsplit_kernel(const float* __restrict__ w) {
    int idx = blockIdx.x * 256 + threadIdx.x;
    if (idx < K * O * C) {
        int k = idx >> 12;
        int o = (idx >> 6) & 63;
        int c = idx & 63;
        float v = w[(o * C + c) * K + k];
        __nv_bfloat16 hi = __float2bfloat16(v);
        __nv_bfloat16 lo = __float2bfloat16(v - __bfloat162float(hi));
        g_wh[idx] = hi;
        g_wl[idx] = lo;
    }
}

// ---------------------------------------------------------------------------
// Kernel C: sampling -> bf16 hi/lo in tiled layout [tile][k][px<128][c<64]
// CTA = (b, ho, 32 wo); warp-task = (k, px); lane = channel pair.
// ---------------------------------------------------------------------------
__global__ __launch_bounds__(256)
void sample_kernel(const float* __restrict__ offset,
                   const float* __restrict__ mask) {
    const int wo0 = blockIdx.x * TILE_P;
    const int ho  = blockIdx.y;
    const int b   = blockIdx.z;
    const int warpId = threadIdx.x >> 5;
    const int lane   = threadIdx.x & 31;

    const float* xb = g_xt + b * HW * C;
    const int coff = lane * 2;

    #pragma unroll 2
    for (int i = 0; i < (K * TILE_P) / 8; i++) {   // 36 tasks per warp
        int t = warpId * 36 + i;
        int k = t >> 5;
        int p = t & 31;
        int wo = wo0 + p;

        float offy = __ldg(&offset[((b * 2 * K + 2 * k    ) * H + ho) * W + wo]);
        float offx = __ldg(&offset[((b * 2 * K + 2 * k + 1) * H + ho) * W + wo]);
        float m    = __ldg(&mask  [((b * K + k) * H + ho) * W + wo]);
        float py = offy + (float)(k / KW) + (float)(ho - 1);   // sh=dh=1, ph=1
        float px = offx + (float)(k % KW) + (float)(wo - 1);
        float y0f = floorf(py), x0f = floorf(px);
        float ly = py - y0f, lx = px - x0f;
        int y0 = (int)y0f, x0 = (int)x0f;
        float w00 = (1.f - ly) * (1.f - lx) * m;
        float w01 = (1.f - ly) * lx * m;
        float w10 = ly * (1.f - lx) * m;
        float w11 = ly * lx * m;

        bool yv0 = (unsigned)y0 < H;
        bool yv1 = (unsigned)(y0 + 1) < H;
        bool xv0 = (unsigned)x0 < W;
        bool xv1 = (unsigned)(x0 + 1) < W;

        float2 v00 = {0.f, 0.f}, v01 = {0.f, 0.f}, v10 = {0.f, 0.f}, v11 = {0.f, 0.f};
        if (yv0 && xv0) v00 = *(const float2*)(xb + ((y0    ) * W + x0    ) * C + coff);
        if (yv0 && xv1) v01 = *(const float2*)(xb + ((y0    ) * W + x0 + 1) * C + coff);
        if (yv1 && xv0) v10 = *(const float2*)(xb + ((y0 + 1) * W + x0    ) * C + coff);
        if (yv1 && xv1) v11 = *(const float2*)(xb + ((y0 + 1) * W + x0 + 1) * C + coff);

        float rx = w00 * v00.x + w01 * v01.x + w10 * v10.x + w11 * v11.x;
        float ry = w00 * v00.y + w01 * v01.y + w10 * v10.y + w11 * v11.y;

        __nv_bfloat16 hx = __float2bfloat16(rx);
        __nv_bfloat16 hy = __float2bfloat16(ry);
        __nv_bfloat16 lxb = __float2bfloat16(rx - __bfloat162float(hx));
        __nv_bfloat16 lyb = __float2bfloat16(ry - __bfloat162float(hy));

        int P = b * HW + ho * W + wo;
        size_t e = ((size_t)((P >> 7) * NCH + k)) * (GPX * C) + (P & 127) * C + coff;
        *(__nv_bfloat162*)(g_vh + e) = __nv_bfloat162(hx, hy);
        *(__nv_bfloat162*)(g_vl + e) = __nv_bfloat162(lxb, lyb);
    }
}

// ---------------------------------------------------------------------------
// Kernel D: HMMA GEMM via mma.sync (bf16 hi/lo 3-term split, fp32 accum).
// CTA = 128px x 64o tile; 8 warps = 4(px) x 2(o); warp tile 32x32.
// ---------------------------------------------------------------------------
#define SA_H 0
#define SA_L (GPX * SSTR)              // 18432
#define SB_H (2 * GPX * SSTR)          // 36864
#define SB_L (2 * GPX * SSTR + O * SSTR)   // 46080
#define SME_TOT (2 * GPX * SSTR + 2 * O * SSTR)  // 55296

__global__ __launch_bounds__(256)
void gemm_mma_kernel(const float* __restrict__ bias, float* __restrict__ out) {
    extern __shared__ char smem[];
    const uint32_t sb = smem_u32(smem);
    const int tid  = threadIdx.x;
    const int wid  = tid >> 5;
    const int lane = tid & 31;
    const int tile = blockIdx.x;

    const int px0 = (wid & 3) * 32;    // warp px base
    const int o0  = (wid >> 2) * 32;   // warp o base

    float acc[2][4][4];                // [mt][nt][reg]
    #pragma unroll
    for (int i = 0; i < 2; i++)
        #pragma unroll
        for (int j = 0; j < 4; j++)
            #pragma unroll
            for (int r = 0; r < 4; r++) acc[i][j][r] = 0.f;

    const uint4* vh4 = (const uint4*)g_vh;
    const uint4* vl4 = (const uint4*)g_vl;
    const uint4* wh4 = (const uint4*)g_wh;
    const uint4* wl4 = (const uint4*)g_wl;

    // ldmatrix source addresses (per lane)
    const uint32_t aAddrH = sb + SA_H + (px0 + (lane & 15)) * SSTR + (lane >> 4) * 16;
    const uint32_t aAddrL = aAddrH + (SA_L - SA_H);
    const uint32_t bAddrH = sb + SB_H + (o0 + (lane & 7)) * SSTR + ((lane >> 3) & 1) * 16;
    const uint32_t bAddrL = bAddrH + (SB_L - SB_H);

    #pragma unroll 1
    for (int ch = 0; ch < NCH; ch++) {
        if (ch) __syncthreads();
        // ---- stage A hi/lo: 1024 uint4 each, rows of 8 uint4 -> padded rows
        size_t abase = (size_t)(tile * NCH + ch) * 1024;
        #pragma unroll
        for (int j = 0; j < 4; j++) {
            int e = j * 256 + tid;
            uint32_t off = (e >> 3) * SSTR + (e & 7) * 16;
            *(uint4*)(smem + SA_H + off) = vh4[abase + e];
            *(uint4*)(smem + SA_L + off) = vl4[abase + e];
        }
        // ---- stage B hi/lo: 512 uint4 each
        size_t bbase = (size_t)ch * 512;
        #pragma unroll
        for (int j = 0; j < 2; j++) {
            int e = j * 256 + tid;
            uint32_t off = (e >> 3) * SSTR + (e & 7) * 16;
            *(uint4*)(smem + SB_H + off) = wh4[bbase + e];
            *(uint4*)(smem + SB_L + off) = wl4[bbase + e];
        }
        __syncthreads();

        #pragma unroll
        for (int s = 0; s < 4; s++) {         // 4 K-steps of 16
            uint32_t ah[2][4], al[2][4], bh[4][2], bl[4][2];
            #pragma unroll
            for (int mt = 0; mt < 2; mt++) {
                ldsm_x4(ah[mt], aAddrH + mt * 16 * SSTR + s * 32);
                ldsm_x4(al[mt], aAddrL + mt * 16 * SSTR + s * 32);
            }
            #pragma unroll
            for (int nt = 0; nt < 4; nt++) {
                ldsm_x2(bh[nt], bAddrH + nt * 8 * SSTR + s * 32);
                ldsm_x2(bl[nt], bAddrL + nt * 8 * SSTR + s * 32);
            }
            #pragma unroll
            for (int mt = 0; mt < 2; mt++)
                #pragma unroll
                for (int nt = 0; nt < 4; nt++) {
                    mma16816(acc[mt][nt], ah[mt], bh[nt]);
                    mma16816(acc[mt][nt], al[mt], bh[nt]);
                    mma16816(acc[mt][nt], ah[mt], bl[nt]);
                }
        }
    }

    // ---- epilogue: D[px][o]; lane l -> px = l/4 (+8), o = (l%4)*2 (+1)
    const int b   = tile >> 7;                 // tile*128 / 16384
    const int hw0 = (tile << 7) & (HW - 1);
    float* ob = out + (size_t)b * O * HW + hw0;
    #pragma unroll
    for (int nt = 0; nt < 4; nt++) {
        int o_b = o0 + nt * 8 + (lane & 3) * 2;
        float bv0 = __ldg(&bias[o_b]);
        float bv1 = __ldg(&bias[o_b + 1]);
        #pragma unroll
        for (int mt = 0; mt < 2; mt++) {
            int px = px0 + mt * 16 + (lane >> 2);
            float* p0 = ob + (size_t)o_b * HW + px;
            p0[0]            = acc[mt][nt][0] + bv0;
            p0[HW]           = acc[mt][nt][1] + bv1;
            p0[8]            = acc[mt][nt][2] + bv0;
            p0[HW + 8]       = acc[mt][nt][3] + bv1;
        }
    }
}

// ---------------------------------------------------------------------------
extern "C" void kernel_launch(void* const* d_in, const int* in_sizes, int n_in,
                              void* d_out, int out_size) {
    const float* x      = (const float*)d_in[0];
    const float* offset = (const float*)d_in[1];
    const float* mask   = (const float*)d_in[2];
    const float* weight = (const float*)d_in[3];
    const float* bias   = (const float*)d_in[4];
    float* out = (float*)d_out;

    {   // A: transpose to NHWC
        dim3 grid(HW / 32, C / 32, B);
        dim3 block(32, 8);
        transpose_kernel<<<grid, block>>>(x);
    }
    {   // B: weight split/repack
        wsplit_kernel<<<(K * O * C + 255) / 256, 256>>>(weight);
    }
    {   // C: sampling (bf16 hi/lo, tiled layout)
        dim3 grid(W / TILE_P, H, B);
        sample_kernel<<<grid, 256>>>(offset, mask);
    }
    {   // D: HMMA GEMM
        cudaFuncSetAttribute(gemm_mma_kernel,
                             cudaFuncAttributeMaxDynamicSharedMemorySize, SME_TOT);
        gemm_mma_kernel<<<NTILES, 256, SME_TOT>>>(bias, out);
    }
}

// round 14
// speedup vs baseline: 3.6142x; 1.3312x over previous
#include <cuda_runtime.h>
#include <cuda_bf16.h>
#include <cstdint>

// Problem constants
#define B  4
#define C  64
#define H  128
#define W  128
#define O  64
#define KH 3
#define KW 3
#define K  9
#define CK (C*K)      // 576
#define HW (H*W)      // 16384
#define NPIX (B*HW)   // 65536

#define TILE_P 32         // sampler tile
#define GPX 128           // GEMM pixels per tile (one image row)
#define NTILES (NPIX/GPX) // 512
#define NCH 9             // kc chunks of 64 (== tap k)

// Padded smem row stride: 64 bf16 + 8 pad = 72 bf16 = 144 bytes
#define SSTR 144

// Scratch (__device__ globals per allocation rules)
__device__ float          g_xt[B * HW * C];        // NHWC input fp32, 16.8MB
__device__ __nv_bfloat16  g_vh[(size_t)NPIX * CK]; // val hi, [tile][k][px][c], 75.5MB
__device__ __nv_bfloat16  g_vl[(size_t)NPIX * CK]; // val lo
__device__ __nv_bfloat16  g_wh[K * O * C];         // weight hi, [k][o][c]
__device__ __nv_bfloat16  g_wl[K * O * C];         // weight lo

// ---------------- PTX helpers ----------------
__device__ __forceinline__ uint32_t smem_u32(const void* p) {
    uint32_t a;
    asm("{ .reg .u64 t; cvta.to.shared.u64 t, %1; cvt.u32.u64 %0, t; }" : "=r"(a) : "l"(p));
    return a;
}
__device__ __forceinline__ void ldsm_x4(uint32_t* r, uint32_t addr) {
    asm volatile("ldmatrix.sync.aligned.m8n8.x4.shared.b16 {%0,%1,%2,%3}, [%4];"
        : "=r"(r[0]), "=r"(r[1]), "=r"(r[2]), "=r"(r[3]) : "r"(addr));
}
__device__ __forceinline__ void ldsm_x2(uint32_t* r, uint32_t addr) {
    asm volatile("ldmatrix.sync.aligned.m8n8.x2.shared.b16 {%0,%1}, [%2];"
        : "=r"(r[0]), "=r"(r[1]) : "r"(addr));
}
__device__ __forceinline__ void mma16816(float* d, const uint32_t* a, const uint32_t* b) {
    asm volatile("mma.sync.aligned.m16n8k16.row.col.f32.bf16.bf16.f32 "
        "{%0,%1,%2,%3}, {%4,%5,%6,%7}, {%8,%9}, {%0,%1,%2,%3};"
        : "+f"(d[0]), "+f"(d[1]), "+f"(d[2]), "+f"(d[3])
        : "r"(a[0]), "r"(a[1]), "r"(a[2]), "r"(a[3]), "r"(b[0]), "r"(b[1]));
}
__device__ __forceinline__ void cp16(uint32_t saddr, const void* gptr) {
    asm volatile("cp.async.cg.shared.global [%0], [%1], 16;" :: "r"(saddr), "l"(gptr));
}

// ---------------------------------------------------------------------------
// Kernel A: NCHW -> NHWC transpose (fp32, sampler input)
// ---------------------------------------------------------------------------
__global__ void transpose_kernel(const float* __restrict__ x) {
    __shared__ float tile[32][33];
    int b  = blockIdx.z;
    int c0 = blockIdx.y * 32;
    int s0 = blockIdx.x * 32;
    int tx = threadIdx.x, ty = threadIdx.y;   // block (32, 8)
    #pragma unroll
    for (int i = 0; i < 32; i += 8)
        tile[ty + i][tx] = x[(b * C + c0 + ty + i) * HW + s0 + tx];
    __syncthreads();
    #pragma unroll
    for (int i = 0; i < 32; i += 8)
        g_xt[(b * HW + s0 + ty + i) * C + c0 + tx] = tile[tx][ty + i];
}

// ---------------------------------------------------------------------------
// Kernel B: weight split+repack  W[o][c][k] -> Wh/Wl [k][o][c] bf16
// ---------------------------------------------------------------------------
__global__ void wsplit_kernel(const float* __restrict__ w) {
    int idx = blockIdx.x * 256 + threadIdx.x;
    if (idx < K * O * C) {
        int k = idx >> 12;
        int o = (idx >> 6) & 63;
        int c = idx & 63;
        float v = w[(o * C + c) * K + k];
        __nv_bfloat16 hi = __float2bfloat16(v);
        __nv_bfloat16 lo = __float2bfloat16(v - __bfloat162float(hi));
        g_wh[idx] = hi;
        g_wl[idx] = lo;
    }
}

// ---------------------------------------------------------------------------
// Kernel C: sampling -> bf16 hi/lo, tiled layout [tile][k][px<128][c<64]
// Phase 0: coalesced param precompute into smem. Phase 1: unroll-4 gathers.
// ---------------------------------------------------------------------------
__global__ __launch_bounds__(256)
void sample_kernel(const float* __restrict__ offset,
                   const float* __restrict__ mask) {
    __shared__ int   s_y0[K * TILE_P], s_x0[K * TILE_P];
    __shared__ float s_w00[K * TILE_P], s_w01[K * TILE_P],
                     s_w10[K * TILE_P], s_w11[K * TILE_P];

    const int wo0 = blockIdx.x * TILE_P;
    const int ho  = blockIdx.y;
    const int b   = blockIdx.z;
    const int tid    = threadIdx.x;
    const int warpId = tid >> 5;
    const int lane   = tid & 31;

    // ---- Phase 0: coalesced loads (lane = pixel), params into smem
    for (int t = tid; t < K * TILE_P; t += 256) {
        int k = t >> 5;
        int p = t & 31;
        int wo = wo0 + p;
        float offy = offset[((b * 2 * K + 2 * k    ) * H + ho) * W + wo];
        float offx = offset[((b * 2 * K + 2 * k + 1) * H + ho) * W + wo];
        float m    = mask  [((b * K + k) * H + ho) * W + wo];
        float py = offy + (float)(k / KW) + (float)(ho - 1);   // sh=dh=1, ph=1
        float px = offx + (float)(k % KW) + (float)(wo - 1);
        float y0f = floorf(py), x0f = floorf(px);
        float ly = py - y0f, lx = px - x0f;
        s_y0[t] = (int)y0f;
        s_x0[t] = (int)x0f;
        s_w00[t] = (1.f - ly) * (1.f - lx) * m;
        s_w01[t] = (1.f - ly) * lx * m;
        s_w10[t] = ly * (1.f - lx) * m;
        s_w11[t] = ly * lx * m;
    }
    __syncthreads();

    const float* xb = g_xt + b * HW * C;
    const int coff = lane * 2;

    // ---- Phase 1: gathers; params via broadcast LDS; deep unroll for MLP
    #pragma unroll 4
    for (int i = 0; i < (K * TILE_P) / 8; i++) {   // 36 tasks per warp
        int t = warpId * 36 + i;
        int k = t >> 5;
        int p = t & 31;
        int y0 = s_y0[t];
        int x0 = s_x0[t];
        float w00 = s_w00[t], w01 = s_w01[t], w10 = s_w10[t], w11 = s_w11[t];

        bool yv0 = (unsigned)y0 < H;
        bool yv1 = (unsigned)(y0 + 1) < H;
        bool xv0 = (unsigned)x0 < W;
        bool xv1 = (unsigned)(x0 + 1) < W;

        float2 v00 = {0.f, 0.f}, v01 = {0.f, 0.f}, v10 = {0.f, 0.f}, v11 = {0.f, 0.f};
        if (yv0 && xv0) v00 = *(const float2*)(xb + ((y0    ) * W + x0    ) * C + coff);
        if (yv0 && xv1) v01 = *(const float2*)(xb + ((y0    ) * W + x0 + 1) * C + coff);
        if (yv1 && xv0) v10 = *(const float2*)(xb + ((y0 + 1) * W + x0    ) * C + coff);
        if (yv1 && xv1) v11 = *(const float2*)(xb + ((y0 + 1) * W + x0 + 1) * C + coff);

        float rx = w00 * v00.x + w01 * v01.x + w10 * v10.x + w11 * v11.x;
        float ry = w00 * v00.y + w01 * v01.y + w10 * v10.y + w11 * v11.y;

        __nv_bfloat16 hx = __float2bfloat16(rx);
        __nv_bfloat16 hy = __float2bfloat16(ry);
        __nv_bfloat16 lxb = __float2bfloat16(rx - __bfloat162float(hx));
        __nv_bfloat16 lyb = __float2bfloat16(ry - __bfloat162float(hy));

        int P = b * HW + ho * W + wo0 + p;
        size_t e = ((size_t)((P >> 7) * NCH + k)) * (GPX * C) + (P & 127) * C + coff;
        *(__nv_bfloat162*)(g_vh + e) = __nv_bfloat162(hx, hy);
        *(__nv_bfloat162*)(g_vl + e) = __nv_bfloat162(lxb, lyb);
    }
}

// ---------------------------------------------------------------------------
// Kernel D: HMMA GEMM, cp.async double-buffered.
// CTA = 128px x 64o tile; 8 warps = 4(px) x 2(o); warp tile 32x32.
// ---------------------------------------------------------------------------
#define SA_H 0
#define SA_L (GPX * SSTR)                       // 18432
#define SB_H (2 * GPX * SSTR)                   // 36864
#define SB_L (2 * GPX * SSTR + O * SSTR)        // 46080
#define BUFSZ (2 * GPX * SSTR + 2 * O * SSTR)   // 55296
#define SME_TOT (2 * BUFSZ)                     // 110592

__global__ __launch_bounds__(256, 2)
void gemm_mma_kernel(const float* __restrict__ bias, float* __restrict__ out) {
    extern __shared__ char smem[];
    const uint32_t sb = smem_u32(smem);
    const int tid  = threadIdx.x;
    const int wid  = tid >> 5;
    const int lane = tid & 31;
    const int tile = blockIdx.x;

    const int px0 = (wid & 3) * 32;    // warp px base
    const int o0  = (wid >> 2) * 32;   // warp o base

    float acc[2][4][4];
    #pragma unroll
    for (int i = 0; i < 2; i++)
        #pragma unroll
        for (int j = 0; j < 4; j++)
            #pragma unroll
            for (int r = 0; r < 4; r++) acc[i][j][r] = 0.f;

    const uint4* vh4 = (const uint4*)g_vh;
    const uint4* vl4 = (const uint4*)g_vl;
    const uint4* wh4 = (const uint4*)g_wh;
    const uint4* wl4 = (const uint4*)g_wl;

    // lane-relative ldmatrix offsets (add buffer base per chunk)
    const uint32_t aOffH = SA_H + (px0 + (lane & 15)) * SSTR + (lane >> 4) * 16;
    const uint32_t aOffL = aOffH + (SA_L - SA_H);
    const uint32_t bOffH = SB_H + (o0 + (lane & 7)) * SSTR + ((lane >> 3) & 1) * 16;
    const uint32_t bOffL = bOffH + (SB_L - SB_H);

    // staging offsets for this thread (4x A-quads, 2x B-quads)
    uint32_t sAoff[4], sBoff[2];
    #pragma unroll
    for (int j = 0; j < 4; j++) {
        int e = j * 256 + tid;
        sAoff[j] = (e >> 3) * SSTR + (e & 7) * 16;
    }
    #pragma unroll
    for (int j = 0; j < 2; j++) {
        int e = j * 256 + tid;
        sBoff[j] = (e >> 3) * SSTR + (e & 7) * 16;
    }

    auto issue = [&](int ch, int buf) {
        uint32_t base = sb + buf * BUFSZ;
        size_t abase = (size_t)(tile * NCH + ch) * 1024;
        #pragma unroll
        for (int j = 0; j < 4; j++) {
            int e = j * 256 + tid;
            cp16(base + SA_H + sAoff[j], vh4 + abase + e);
            cp16(base + SA_L + sAoff[j], vl4 + abase + e);
        }
        size_t bbase = (size_t)ch * 512;
        #pragma unroll
        for (int j = 0; j < 2; j++) {
            int e = j * 256 + tid;
            cp16(base + SB_H + sBoff[j], wh4 + bbase + e);
            cp16(base + SB_L + sBoff[j], wl4 + bbase + e);
        }
        asm volatile("cp.async.commit_group;" ::: "memory");
    };

    issue(0, 0);

    #pragma unroll 1
    for (int ch = 0; ch < NCH; ch++) {
        if (ch + 1 < NCH) {
            issue(ch + 1, (ch + 1) & 1);
            asm volatile("cp.async.wait_group 1;" ::: "memory");
        } else {
            asm volatile("cp.async.wait_group 0;" ::: "memory");
        }
        __syncthreads();

        const uint32_t base = sb + (ch & 1) * BUFSZ;
        const uint32_t aH = base + aOffH, aL = base + aOffL;
        const uint32_t bH = base + bOffH, bL = base + bOffL;

        #pragma unroll
        for (int s = 0; s < 4; s++) {         // 4 K-steps of 16
            uint32_t ah[2][4], al[2][4], bh[4][2], bl[4][2];
            #pragma unroll
            for (int mt = 0; mt < 2; mt++) {
                ldsm_x4(ah[mt], aH + mt * 16 * SSTR + s * 32);
                ldsm_x4(al[mt], aL + mt * 16 * SSTR + s * 32);
            }
            #pragma unroll
            for (int nt = 0; nt < 4; nt++) {
                ldsm_x2(bh[nt], bH + nt * 8 * SSTR + s * 32);
                ldsm_x2(bl[nt], bL + nt * 8 * SSTR + s * 32);
            }
            #pragma unroll
            for (int mt = 0; mt < 2; mt++)
                #pragma unroll
                for (int nt = 0; nt < 4; nt++) {
                    mma16816(acc[mt][nt], ah[mt], bh[nt]);
                    mma16816(acc[mt][nt], al[mt], bh[nt]);
                    mma16816(acc[mt][nt], ah[mt], bl[nt]);
                }
        }
        __syncthreads();   // compute done before buffer reuse next iteration
    }

    // ---- epilogue: D[px][o]; lane l -> px = l/4 (+8), o = (l%4)*2 (+1)
    const int b   = tile >> 7;
    const int hw0 = (tile << 7) & (HW - 1);
    float* ob = out + (size_t)b * O * HW + hw0;
    #pragma unroll
    for (int nt = 0; nt < 4; nt++) {
        int o_b = o0 + nt * 8 + (lane & 3) * 2;
        float bv0 = __ldg(&bias[o_b]);
        float bv1 = __ldg(&bias[o_b + 1]);
        #pragma unroll
        for (int mt = 0; mt < 2; mt++) {
            int px = px0 + mt * 16 + (lane >> 2);
            float* p0 = ob + (size_t)o_b * HW + px;
            p0[0]      = acc[mt][nt][0] + bv0;
            p0[HW]     = acc[mt][nt][1] + bv1;
            p0[8]      = acc[mt][nt][2] + bv0;
            p0[HW + 8] = acc[mt][nt][3] + bv1;
        }
    }
}

// ---------------------------------------------------------------------------
extern "C" void kernel_launch(void* const* d_in, const int* in_sizes, int n_in,
                              void* d_out, int out_size) {
    const float* x      = (const float*)d_in[0];
    const float* offset = (const float*)d_in[1];
    const float* mask   = (const float*)d_in[2];
    const float* weight = (const float*)d_in[3];
    const float* bias   = (const float*)d_in[4];
    float* out = (float*)d_out;

    {   // A: transpose to NHWC
        dim3 grid(HW / 32, C / 32, B);
        dim3 block(32, 8);
        transpose_kernel<<<grid, block>>>(x);
    }
    {   // B: weight split/repack
        wsplit_kernel<<<(K * O * C + 255) / 256, 256>>>(weight);
    }
    {   // C: sampling (bf16 hi/lo, tiled layout)
        dim3 grid(W / TILE_P, H, B);
        sample_kernel<<<grid, 256>>>(offset, mask);
    }
    {   // D: HMMA GEMM, double-buffered
        cudaFuncSetAttribute(gemm_mma_kernel,
                             cudaFuncAttributeMaxDynamicSharedMemorySize, SME_TOT);
        gemm_mma_kernel<<<NTILES, 256, SME_TOT>>>(bias, out);
    }
}